// round 14
// baseline (speedup 1.0000x reference)
#include <cuda_runtime.h>
#include <math.h>

#define B_SAMPLES 128
#define T_LEN     8192
#define C_CLASSES 64
#define OUT_LEN   8

#define THREADS   256
#define STREAM_CTAS 128                      // streaming CTAs per sample
#define CHUNKS    4                          // topk CTAs per sample
#define CTAS_PER_SAMPLE (STREAM_CTAS + CHUNKS)   // 132
#define CHUNK_LEN (T_LEN / CHUNKS)           // 2048
#define EPT       8
#define L2E       1.4426950408889634f

// Scratch (allocation-free __device__ globals; counters zero-init + self-reset)
__device__ __align__(16) float         g_conf[B_SAMPLES * T_LEN];
__device__ __align__(16) unsigned char g_pred[B_SAMPLES * T_LEN];
__device__ __align__(16) float g_candv[B_SAMPLES * 32];
__device__ __align__(16) int   g_candi[B_SAMPLES * 32];
__device__ int g_cnt[B_SAMPLES];             // streaming-done counter
__device__ int g_mcnt[B_SAMPLES];            // chunk-done counter

__device__ __forceinline__ float ex2_approx(float t) {
    float r;
    asm("ex2.approx.ftz.f32 %0, %1;" : "=f"(r) : "f"(t));
    return r;
}
__device__ __forceinline__ int atom_add_release(int* p, int v) {
    int r;
    asm volatile("atom.release.gpu.global.add.s32 %0, [%1], %2;"
                 : "=r"(r) : "l"(p), "r"(v) : "memory");
    return r;
}
__device__ __forceinline__ int atom_add_acqrel(int* p, int v) {
    int r;
    asm volatile("atom.acq_rel.gpu.global.add.s32 %0, [%1], %2;"
                 : "=r"(r) : "l"(p), "r"(v) : "memory");
    return r;
}
__device__ __forceinline__ int ld_acquire(const int* p) {
    int r;
    asm volatile("ld.acquire.gpu.global.b32 %0, [%1];"
                 : "=r"(r) : "l"(p) : "memory");
    return r;
}

// ---------------------------------------------------------------------------
// One kernel. Per sample b: 128 streaming CTAs (R10's K1 math, untouched)
// + 4 chunk-topk CTAs that spin on b's counter and overlap later streaming.
// Counter resets happen ONLY in the last merging CTA (race-free).
// ---------------------------------------------------------------------------
__global__ __launch_bounds__(THREADS)
void fused_kernel(const float* __restrict__ x, float* __restrict__ out) {
    __shared__ unsigned char spred[CHUNK_LEN];       // 2 KB (topk CTAs only)
    __shared__ float candv[OUT_LEN * 8];
    __shared__ int   candi[OUT_LEN * 8];
    __shared__ int   s_flag;

    const int tid = threadIdx.x;
    const int b   = blockIdx.x / CTAS_PER_SAMPLE;
    const int sub = blockIdx.x % CTAS_PER_SAMPLE;

    if (sub < STREAM_CTAS) {
        // ============== Streaming: 64 positions, 4 threads/position =========
        const int part = tid & 3;
        const size_t pos = (size_t)b * T_LEN + sub * 64 + (tid >> 2);

        const float4* __restrict__ p =
            (const float4*)(x + pos * C_CLASSES + part * 16);
        float4 v0 = p[0], v1 = p[1], v2 = p[2], v3 = p[3];

        float r[16] = {v0.x, v0.y, v0.z, v0.w, v1.x, v1.y, v1.z, v1.w,
                       v2.x, v2.y, v2.z, v2.w, v3.x, v3.y, v3.z, v3.w};

        float m = r[0];
        #pragma unroll
        for (int c = 1; c < 16; c++) m = fmaxf(m, r[c]);

        int am = 0;                                  // first-occurrence argmax
        #pragma unroll
        for (int c = 15; c >= 0; c--)
            if (r[c] >= m) am = c;
        int amg = part * 16 + am;

        #pragma unroll
        for (int d = 1; d < 4; d <<= 1) {
            float om = __shfl_xor_sync(0xFFFFFFFFu, m,   d);
            int   oa = __shfl_xor_sync(0xFFFFFFFFu, amg, d);
            if (om > m || (om == m && oa < amg)) { m = om; amg = oa; }
        }

        float mb = m * L2E;
        float s = 0.0f;
        #pragma unroll
        for (int c = 0; c < 16; c++)
            s += ex2_approx(fmaf(r[c], L2E, -mb));
        #pragma unroll
        for (int d = 1; d < 4; d <<= 1)
            s += __shfl_xor_sync(0xFFFFFFFFu, s, d);

        if (part == 0) {
            g_conf[pos] = __fdividef(1.0f, s);
            g_pred[pos] = (unsigned char)amg;
        }

        __syncthreads();                             // CTA writes complete
        if (tid == 0)
            atom_add_release(&g_cnt[b], 1);          // cheap publish (no MEMBAR)
        return;
    }

    // ================= Chunk top-k: spin until sample b streamed =============
    const int chunk = sub - STREAM_CTAS;
    if (tid == 0) {
        while (ld_acquire(&g_cnt[b]) < STREAM_CTAS) __nanosleep(64);
        // NO reset here — reset races against other chunk CTAs' spins.
    }
    __syncthreads();                                 // acquire propagates CTA-wide

    const int lane = tid & 31;
    const int wid  = tid >> 5;
    const size_t coff = (size_t)b * T_LEN + chunk * CHUNK_LEN;
    const int tloc = tid * EPT;
    const int gt0  = chunk * CHUNK_LEN + tloc;

    // Front-batched loads (mostly L2-hot: just produced)
    uint2  pv2 = ((const uint2*)(g_pred + coff))[tid];
    float4 c0  = ((const float4*)(g_conf + coff))[tid * 2];
    float4 c1  = ((const float4*)(g_conf + coff))[tid * 2 + 1];
    unsigned char prev = 0;
    if (tloc == 0 && gt0 > 0) prev = g_pred[coff - 1];

    ((uint2*)spred)[tid] = pv2;
    __syncthreads();

    unsigned char pb[EPT];
    pb[0] = (unsigned char)(pv2.x);        pb[1] = (unsigned char)(pv2.x >> 8);
    pb[2] = (unsigned char)(pv2.x >> 16);  pb[3] = (unsigned char)(pv2.x >> 24);
    pb[4] = (unsigned char)(pv2.y);        pb[5] = (unsigned char)(pv2.y >> 8);
    pb[6] = (unsigned char)(pv2.y >> 16);  pb[7] = (unsigned char)(pv2.y >> 24);
    float cf[EPT] = {c0.x, c0.y, c0.z, c0.w, c1.x, c1.y, c1.z, c1.w};

    if (tloc > 0) prev = spred[tloc - 1];
    else if (gt0 == 0) prev = (unsigned char)(pb[0] ^ 1);

    float lv[EPT];
    #pragma unroll
    for (int j = 0; j < EPT; j++) {
        unsigned char cur = pb[j];
        unsigned char before = (j == 0) ? prev : pb[j - 1];
        float v = -INFINITY;
        if (cur != before || (gt0 + j == 0)) {
            int cnt = 1;
            int jj = j + 1;
            while (jj < EPT && pb[jj] == cur) { cnt++; jj++; }
            if (jj == EPT) {                                    // smem tail
                int e = tloc + EPT;
                while (e < CHUNK_LEN && spred[e] == cur) { cnt++; e++; }
                if (e == CHUNK_LEN) {                           // global tail
                    size_t ge = coff + CHUNK_LEN;
                    size_t gend = (size_t)b * T_LEN + T_LEN;
                    while (ge < gend && g_pred[ge] == cur) { cnt++; ge++; }
                }
            }
            v = cf[j] * (float)cnt;
        }
        lv[j] = v;
    }

    // ---- per-warp top-8 ----
    #pragma unroll
    for (int k = 0; k < OUT_LEN; k++) {
        float bv = lv[0];
        int   bj = 0;
        #pragma unroll
        for (int j = 1; j < EPT; j++)
            if (lv[j] > bv) { bv = lv[j]; bj = j; }
        int bi = gt0 + bj;

        #pragma unroll
        for (int d = 16; d > 0; d >>= 1) {
            float ov = __shfl_xor_sync(0xFFFFFFFFu, bv, d);
            int   oi = __shfl_xor_sync(0xFFFFFFFFu, bi, d);
            if (ov > bv || (ov == bv && oi < bi)) { bv = ov; bi = oi; }
        }
        if (lane == 0) { candv[k * 8 + wid] = bv; candi[k * 8 + wid] = bi; }
        if (((bi - chunk * CHUNK_LEN) >> 3) == tid)
            lv[bi & (EPT - 1)] = -INFINITY;
    }
    __syncthreads();

    // ---- warp 0: merge 8x8 -> chunk finalists (to global) ----
    if (wid == 0) {
        float cv[OUT_LEN]; int ci[OUT_LEN];
        #pragma unroll
        for (int r = 0; r < OUT_LEN; r++) {
            if (lane < 8) { cv[r] = candv[r * 8 + lane]; ci[r] = candi[r * 8 + lane]; }
            else          { cv[r] = -INFINITY;           ci[r] = 0x7FFFFFFF; }
        }
        #pragma unroll
        for (int k = 0; k < OUT_LEN; k++) {
            float bv = cv[0]; int bi = ci[0], br = 0;
            #pragma unroll
            for (int r = 1; r < OUT_LEN; r++)
                if (cv[r] > bv) { bv = cv[r]; bi = ci[r]; br = r; }
            float mv = bv; int mi = bi;
            #pragma unroll
            for (int d = 16; d > 0; d >>= 1) {
                float ov = __shfl_xor_sync(0xFFFFFFFFu, mv, d);
                int   oi = __shfl_xor_sync(0xFFFFFFFFu, mi, d);
                if (ov > mv || (ov == mv && oi < mi)) { mv = ov; mi = oi; }
            }
            if (lane == 0) {
                int slot = b * 32 + chunk * OUT_LEN + k;
                g_candv[slot] = mv;
                g_candi[slot] = isinf(mv) ? 0x7FFFFFFF : mi;
            }
            if (bv == mv && bi == mi) { cv[br] = -INFINITY; ci[br] = 0x7FFFFFFF; }
        }
    }
    __syncthreads();                                 // candidate writes done

    // ---- last chunk CTA of this sample merges 32 -> output ----
    if (tid == 0) {
        int old = atom_add_acqrel(&g_mcnt[b], 1);
        int last = (old == CHUNKS - 1);
        if (last) {
            // Safe reset point: all 4 chunk CTAs have passed their spin
            // (their g_mcnt add happens-after the spin) and all stream CTAs
            // have incremented g_cnt. Reset both for graph replay.
            g_mcnt[b] = 0;
            g_cnt[b]  = 0;
        }
        s_flag = last;
    }
    __syncthreads();
    if (!s_flag) return;

    if (wid == 0) {
        float v = g_candv[b * 32 + lane];
        int   i = g_candi[b * 32 + lane];

        float resv[OUT_LEN]; int resi[OUT_LEN];
        #pragma unroll
        for (int k = 0; k < OUT_LEN; k++) {
            float wv = v; int wi = i;
            #pragma unroll
            for (int d = 16; d > 0; d >>= 1) {
                float ov = __shfl_xor_sync(0xFFFFFFFFu, wv, d);
                int   oi = __shfl_xor_sync(0xFFFFFFFFu, wi, d);
                if (ov > wv || (ov == wv && oi < wi)) { wv = ov; wi = oi; }
            }
            resv[k] = wv; resi[k] = wi;
            if (v == wv && i == wi) { v = -INFINITY; i = 0x7FFFFFFF; }
        }
        if (lane < OUT_LEN) {
            float rv = resv[lane];
            float o = 0.0f;                          // pad-with-zero path
            if (isfinite(rv)) o = (float)g_pred[(size_t)b * T_LEN + resi[lane]];
            out[(size_t)b * OUT_LEN + lane] = o;
        }
    }
}

// ---------------------------------------------------------------------------
extern "C" void kernel_launch(void* const* d_in, const int* in_sizes, int n_in,
                              void* d_out, int out_size) {
    const float* x = (const float*)d_in[0];
    float* out = (float*)d_out;

    fused_kernel<<<B_SAMPLES * CTAS_PER_SAMPLE, THREADS>>>(x, out);
}

// round 15
// speedup vs baseline: 1.3033x; 1.3033x over previous
#include <cuda_runtime.h>
#include <math.h>

#define B_SAMPLES 128
#define T_LEN     8192
#define C_CLASSES 64
#define OUT_LEN   8

#define K1_THREADS 256
#define K2_THREADS 1024
#define EPT 8                                    // contiguous elems per thread
#define L2E 1.4426950408889634f

// Scratch (allocation-free __device__ globals)
__device__ __align__(16) float         g_conf[B_SAMPLES * T_LEN];
__device__ __align__(16) unsigned char g_pred[B_SAMPLES * T_LEN];

__device__ __forceinline__ float ex2_approx(float t) {
    float r;
    asm("ex2.approx.ftz.f32 %0, %1;" : "=f"(r) : "f"(t));
    return r;
}
// L2 evict-last stores for the 5MB conf/pred working set (matches R10 best)
__device__ __forceinline__ unsigned long long mk_evict_last_policy() {
    unsigned long long pol;
    asm("createpolicy.fractional.L2::evict_last.b64 %0, 1.0;" : "=l"(pol));
    return pol;
}
__device__ __forceinline__ void st_el_f32(float* p, float v, unsigned long long pol) {
    asm volatile("st.global.L2::cache_hint.f32 [%0], %1, %2;"
                 :: "l"(p), "f"(v), "l"(pol) : "memory");
}
__device__ __forceinline__ void st_el_u8(unsigned char* p, unsigned short v,
                                         unsigned long long pol) {
    asm volatile("st.global.L2::cache_hint.u8 [%0], %1, %2;"
                 :: "l"(p), "h"(v), "l"(pol) : "memory");
}

// ---------------------------------------------------------------------------
// K1: softmax confidence + argmax. Full-chip grid (16384 x 256).
// NEW layout: 16 lanes per position. Every LDG.128 is warp-contiguous 512B
// (4 lines -> 4 L1 wavefronts, vs 16 before). 4 loads front-batched (MLP=4).
// Warp covers 8 positions = 2KB; load i holds positions 2i (lanes 0-15) and
// 2i+1 (lanes 16-31), class chunk (lane&15)*4.
// ---------------------------------------------------------------------------
__global__ __launch_bounds__(K1_THREADS)
void softmax_conf_kernel(const float* __restrict__ x) {
    const int lane = threadIdx.x & 31;
    const int w    = threadIdx.x >> 5;
    const size_t pos0  = (size_t)blockIdx.x * 64 + w * 8;   // warp's 8 positions
    const size_t base4 = pos0 * (C_CLASSES / 4);            // float4 index

    const float4* __restrict__ xb4 = (const float4*)x;
    float4 F[4];
    #pragma unroll
    for (int i = 0; i < 4; i++)
        F[i] = xb4[base4 + i * 32 + lane];                  // 512B contiguous

    const unsigned long long pol = mk_evict_last_policy();

    #pragma unroll
    for (int i = 0; i < 4; i++) {
        float4 f = F[i];

        // Thread-local max + first-occurrence argmax within 4 classes
        float m4 = fmaxf(fmaxf(f.x, f.y), fmaxf(f.z, f.w));
        int am = (f.x >= m4) ? 0 : (f.y >= m4) ? 1 : (f.z >= m4) ? 2 : 3;

        // Max over the 16 lanes of this position (xor<16 stays in half)
        float m = m4;
        #pragma unroll
        for (int d = 1; d < 16; d <<= 1)
            m = fmaxf(m, __shfl_xor_sync(0xFFFFFFFFu, m, d));

        // Argmax: lowest lane holding the max (lane order == class order)
        unsigned bal = __ballot_sync(0xFFFFFFFFu, m4 == m);
        int g = lane & 16;
        unsigned half = (bal >> g) & 0xFFFFu;
        int src = g + __ffs(half) - 1;
        int cls = ((lane & 15) << 2) + am;
        int wcls = __shfl_sync(0xFFFFFFFFu, cls, src);

        // exp2-based denominator: FFMA + MUFU.EX2 per element
        float mb = m * L2E;
        float s = ex2_approx(fmaf(f.x, L2E, -mb))
                + ex2_approx(fmaf(f.y, L2E, -mb))
                + ex2_approx(fmaf(f.z, L2E, -mb))
                + ex2_approx(fmaf(f.w, L2E, -mb));
        #pragma unroll
        for (int d = 1; d < 16; d <<= 1)
            s += __shfl_xor_sync(0xFFFFFFFFu, s, d);

        if ((lane & 15) == 0) {
            size_t pos = pos0 + 2 * i + (lane >> 4);
            st_el_f32(&g_conf[pos], __fdividef(1.0f, s), pol);
            st_el_u8(&g_pred[pos], (unsigned short)wcls, pol);
        }
    }
}

// ---------------------------------------------------------------------------
// K2: per-sample RLE + top-8 — byte-for-byte the R10 version (11.8us known).
// ---------------------------------------------------------------------------
__global__ __launch_bounds__(K2_THREADS)
void topk_kernel(float* __restrict__ out) {
    __shared__ unsigned char spred[T_LEN];           // 8 KB
    __shared__ float candv[OUT_LEN * 32];            // [round][warp]
    __shared__ int   candi[OUT_LEN * 32];
    __shared__ float outv[OUT_LEN];
    __shared__ int   outi[OUT_LEN];

    const int b    = blockIdx.x;
    const int tid  = threadIdx.x;
    const int lane = tid & 31;
    const int wid  = tid >> 5;
    const size_t off = (size_t)b * T_LEN;
    const int t0 = tid * EPT;

    // ---- Front-batched, unconditional loads ----
    uint2  pv2 = ((const uint2*)(g_pred + off))[tid];
    float4 c0  = ((const float4*)(g_conf + off))[tid * 2];
    float4 c1  = ((const float4*)(g_conf + off))[tid * 2 + 1];

    ((uint2*)spred)[tid] = pv2;
    __syncthreads();

    unsigned char pb[EPT];
    pb[0] = (unsigned char)(pv2.x);        pb[1] = (unsigned char)(pv2.x >> 8);
    pb[2] = (unsigned char)(pv2.x >> 16);  pb[3] = (unsigned char)(pv2.x >> 24);
    pb[4] = (unsigned char)(pv2.y);        pb[5] = (unsigned char)(pv2.y >> 8);
    pb[6] = (unsigned char)(pv2.y >> 16);  pb[7] = (unsigned char)(pv2.y >> 24);
    float cf[EPT] = {c0.x, c0.y, c0.z, c0.w, c1.x, c1.y, c1.z, c1.w};

    unsigned char prev = (tid == 0) ? (unsigned char)(pb[0] ^ 1) : spred[t0 - 1];

    float lv[EPT];
    #pragma unroll
    for (int j = 0; j < EPT; j++) {
        unsigned char cur = pb[j];
        unsigned char before = (j == 0) ? prev : pb[j - 1];
        bool start = (t0 + j == 0) || (cur != before);
        float v = -INFINITY;
        if (start) {
            int cnt = 1;
            int jj = j + 1;
            while (jj < EPT && pb[jj] == cur) { cnt++; jj++; }   // reg scan
            if (jj == EPT) {                                      // rare spill
                int e = t0 + EPT;
                while (e < T_LEN && spred[e] == cur) { cnt++; e++; }
            }
            v = cf[j] * (float)cnt;
        }
        lv[j] = v;
    }

    // ---- Phase A: per-warp top-8 (no barriers) ----
    #pragma unroll
    for (int k = 0; k < OUT_LEN; k++) {
        float bv = lv[0];
        int   bj = 0;
        #pragma unroll
        for (int j = 1; j < EPT; j++)
            if (lv[j] > bv) { bv = lv[j]; bj = j; }   // j asc = index asc
        int bi = t0 + bj;

        #pragma unroll
        for (int d = 16; d > 0; d >>= 1) {
            float ov = __shfl_xor_sync(0xFFFFFFFFu, bv, d);
            int   oi = __shfl_xor_sync(0xFFFFFFFFu, bi, d);
            if (ov > bv || (ov == bv && oi < bi)) { bv = ov; bi = oi; }
        }
        if (lane == 0) {
            candv[k * 32 + wid] = bv;
            candi[k * 32 + wid] = bi;
        }
        if ((bi >> 3) == tid)              // owner invalidates
            lv[bi & (EPT - 1)] = -INFINITY;
    }
    __syncthreads();

    // ---- Phase B: warp 0 merges 32x8 candidates ----
    if (wid == 0) {
        float cv[OUT_LEN];
        int   ci[OUT_LEN];
        #pragma unroll
        for (int r = 0; r < OUT_LEN; r++) {
            cv[r] = candv[r * 32 + lane];
            ci[r] = candi[r * 32 + lane];
        }
        #pragma unroll
        for (int k = 0; k < OUT_LEN; k++) {
            float bv = cv[0];
            int   bi = ci[0], br = 0;
            #pragma unroll
            for (int r = 1; r < OUT_LEN; r++)
                if (cv[r] > bv) { bv = cv[r]; bi = ci[r]; br = r; }
            float mv = bv; int mi = bi;
            #pragma unroll
            for (int d = 16; d > 0; d >>= 1) {
                float ov = __shfl_xor_sync(0xFFFFFFFFu, mv, d);
                int   oi = __shfl_xor_sync(0xFFFFFFFFu, mi, d);
                if (ov > mv || (ov == mv && oi < mi)) { mv = ov; mi = oi; }
            }
            if (lane == 0) { outv[k] = mv; outi[k] = mi; }
            if (bi == mi) cv[br] = -INFINITY;   // unique index -> one owner
        }
    }
    __syncthreads();

    if (tid < OUT_LEN) {
        float v = outv[tid];
        int   i = outi[tid];
        float o = 0.0f;                               // pad-with-zero path
        if (isfinite(v)) o = (float)spred[i];
        out[(size_t)b * OUT_LEN + tid] = o;
    }
}

// ---------------------------------------------------------------------------
extern "C" void kernel_launch(void* const* d_in, const int* in_sizes, int n_in,
                              void* d_out, int out_size) {
    const float* x = (const float*)d_in[0];
    float* out = (float*)d_out;

    softmax_conf_kernel<<<B_SAMPLES * T_LEN / 64, K1_THREADS>>>(x);
    topk_kernel<<<B_SAMPLES, K2_THREADS>>>(out);
}

// round 16
// speedup vs baseline: 1.3952x; 1.0705x over previous
#include <cuda_runtime.h>
#include <math.h>

#define B_SAMPLES 128
#define T_LEN     8192
#define C_CLASSES 64
#define OUT_LEN   8

#define K1_THREADS 256
#define POS_PER_CTA (K1_THREADS / 4)            // 4 threads per position
#define K2_THREADS 1024
#define EPT 8                                    // contiguous elems per thread
#define L2E 1.4426950408889634f

// Scratch (allocation-free __device__ globals)
__device__ __align__(16) float         g_conf[B_SAMPLES * T_LEN];
__device__ __align__(16) unsigned char g_pred[B_SAMPLES * T_LEN];

__device__ __forceinline__ float ex2_approx(float t) {
    float r;
    asm("ex2.approx.ftz.f32 %0, %1;" : "=f"(r) : "f"(t));
    return r;
}
__device__ __forceinline__ unsigned long long mk_evict_last_policy() {
    unsigned long long pol;
    asm("createpolicy.fractional.L2::evict_last.b64 %0, 1.0;" : "=l"(pol));
    return pol;
}
__device__ __forceinline__ void st_el_f32(float* p, float v, unsigned long long pol) {
    asm volatile("st.global.L2::cache_hint.f32 [%0], %1, %2;"
                 :: "l"(p), "f"(v), "l"(pol) : "memory");
}
__device__ __forceinline__ void st_el_u8(unsigned char* p, unsigned short v,
                                         unsigned long long pol) {
    asm volatile("st.global.L2::cache_hint.u8 [%0], %1, %2;"
                 :: "l"(p), "h"(v), "l"(pol) : "memory");
}

// ---------------------------------------------------------------------------
// K1: byte-for-byte the R10 kernel (best known: ~40us, DRAM ~80%).
// ---------------------------------------------------------------------------
__global__ __launch_bounds__(K1_THREADS)
void softmax_conf_kernel(const float* __restrict__ x) {
    const int tid  = threadIdx.x;
    const int part = tid & 3;
    const size_t pos = (size_t)blockIdx.x * POS_PER_CTA + (tid >> 2);

    const float4* __restrict__ p =
        (const float4*)(x + pos * C_CLASSES + part * 16);
    float4 v0 = p[0], v1 = p[1], v2 = p[2], v3 = p[3];

    float r[16] = {v0.x, v0.y, v0.z, v0.w, v1.x, v1.y, v1.z, v1.w,
                   v2.x, v2.y, v2.z, v2.w, v3.x, v3.y, v3.z, v3.w};

    float m = r[0];
    #pragma unroll
    for (int c = 1; c < 16; c++) m = fmaxf(m, r[c]);

    int am = 0;                                   // first-occurrence argmax
    #pragma unroll
    for (int c = 15; c >= 0; c--)
        if (r[c] >= m) am = c;
    int amg = part * 16 + am;

    #pragma unroll
    for (int d = 1; d < 4; d <<= 1) {
        float om = __shfl_xor_sync(0xFFFFFFFFu, m,   d);
        int   oa = __shfl_xor_sync(0xFFFFFFFFu, amg, d);
        if (om > m || (om == m && oa < amg)) { m = om; amg = oa; }
    }

    float mb = m * L2E;
    float s = 0.0f;
    #pragma unroll
    for (int c = 0; c < 16; c++)
        s += ex2_approx(fmaf(r[c], L2E, -mb));
    #pragma unroll
    for (int d = 1; d < 4; d <<= 1)
        s += __shfl_xor_sync(0xFFFFFFFFu, s, d);

    if (part == 0) {
        unsigned long long pol = mk_evict_last_policy();
        st_el_f32(&g_conf[pos], __fdividef(1.0f, s), pol);
        st_el_u8(&g_pred[pos], (unsigned short)amg, pol);
    }
}

// ---------------------------------------------------------------------------
// K2: per-sample RLE + top-8. Same as R10 EXCEPT: consumption is via a
// bitmask with fully static scans -> lv/cv stay in REGISTERS (the R10
// version's dynamic writes lv[bi&7] / cv[br] forced local-memory spills).
// ---------------------------------------------------------------------------
__global__ __launch_bounds__(K2_THREADS)
void topk_kernel(float* __restrict__ out) {
    __shared__ unsigned char spred[T_LEN];           // 8 KB
    __shared__ float candv[OUT_LEN * 32];            // [round][warp]
    __shared__ int   candi[OUT_LEN * 32];
    __shared__ float outv[OUT_LEN];
    __shared__ int   outi[OUT_LEN];

    const int b    = blockIdx.x;
    const int tid  = threadIdx.x;
    const int lane = tid & 31;
    const int wid  = tid >> 5;
    const size_t off = (size_t)b * T_LEN;
    const int t0 = tid * EPT;

    // ---- Front-batched, unconditional loads ----
    uint2  pv2 = ((const uint2*)(g_pred + off))[tid];
    float4 c0  = ((const float4*)(g_conf + off))[tid * 2];
    float4 c1  = ((const float4*)(g_conf + off))[tid * 2 + 1];

    ((uint2*)spred)[tid] = pv2;
    __syncthreads();

    unsigned char pb[EPT];
    pb[0] = (unsigned char)(pv2.x);        pb[1] = (unsigned char)(pv2.x >> 8);
    pb[2] = (unsigned char)(pv2.x >> 16);  pb[3] = (unsigned char)(pv2.x >> 24);
    pb[4] = (unsigned char)(pv2.y);        pb[5] = (unsigned char)(pv2.y >> 8);
    pb[6] = (unsigned char)(pv2.y >> 16);  pb[7] = (unsigned char)(pv2.y >> 24);
    float cf[EPT] = {c0.x, c0.y, c0.z, c0.w, c1.x, c1.y, c1.z, c1.w};

    unsigned char prev = (tid == 0) ? (unsigned char)(pb[0] ^ 1) : spred[t0 - 1];

    float lv[EPT];
    #pragma unroll
    for (int j = 0; j < EPT; j++) {
        unsigned char cur = pb[j];
        unsigned char before = (j == 0) ? prev : pb[j - 1];
        bool start = (t0 + j == 0) || (cur != before);
        float v = -INFINITY;
        if (start) {
            int cnt = 1;
            int jj = j + 1;
            while (jj < EPT && pb[jj] == cur) { cnt++; jj++; }   // reg scan
            if (jj == EPT) {                                      // rare spill
                int e = t0 + EPT;
                while (e < T_LEN && spred[e] == cur) { cnt++; e++; }
            }
            v = cf[j] * (float)cnt;
        }
        lv[j] = v;
    }

    // ---- Phase A: per-warp top-8 (mask-consume, static indexing only) ----
    unsigned mask = 0;                   // bit j set = lv[j] consumed
    #pragma unroll
    for (int k = 0; k < OUT_LEN; k++) {
        float bv = -INFINITY;
        int   bj = 0;
        #pragma unroll
        for (int j = 0; j < EPT; j++)    // j asc = index asc (first-max tie)
            if (!(mask & (1u << j)) && lv[j] > bv) { bv = lv[j]; bj = j; }
        int bi = t0 + bj;

        #pragma unroll
        for (int d = 16; d > 0; d >>= 1) {
            float ov = __shfl_xor_sync(0xFFFFFFFFu, bv, d);
            int   oi = __shfl_xor_sync(0xFFFFFFFFu, bi, d);
            if (ov > bv || (ov == bv && oi < bi)) { bv = ov; bi = oi; }
        }
        if (lane == 0) {
            candv[k * 32 + wid] = bv;
            candi[k * 32 + wid] = bi;
        }
        if ((bi >> 3) == tid)            // owner consumes (no dynamic write)
            mask |= 1u << (bi & (EPT - 1));
    }
    __syncthreads();

    // ---- Phase B: warp 0 merges 32x8 candidates (mask-consume) ----
    if (wid == 0) {
        float cv[OUT_LEN];
        int   ci[OUT_LEN];
        #pragma unroll
        for (int r = 0; r < OUT_LEN; r++) {
            cv[r] = candv[r * 32 + lane];
            ci[r] = candi[r * 32 + lane];
        }
        unsigned m2 = 0;
        #pragma unroll
        for (int k = 0; k < OUT_LEN; k++) {
            // Per-lane candidates are value-desc / index-asc on ties: strict >
            // keeps the lowest-index tie, matching lax.top_k.
            float bv = -INFINITY;
            int   bi = 0x7FFFFFFF, br = 0;
            #pragma unroll
            for (int r = 0; r < OUT_LEN; r++)
                if (!(m2 & (1u << r)) && cv[r] > bv) {
                    bv = cv[r]; bi = ci[r]; br = r;
                }
            float mv = bv; int mi = bi;
            #pragma unroll
            for (int d = 16; d > 0; d >>= 1) {
                float ov = __shfl_xor_sync(0xFFFFFFFFu, mv, d);
                int   oi = __shfl_xor_sync(0xFFFFFFFFu, mi, d);
                if (ov > mv || (ov == mv && oi < mi)) { mv = ov; mi = oi; }
            }
            if (lane == 0) { outv[k] = mv; outi[k] = mi; }
            if (bv == mv && bi == mi)    // unique index -> exactly one owner
                m2 |= 1u << br;
        }
    }
    __syncthreads();

    if (tid < OUT_LEN) {
        float v = outv[tid];
        int   i = outi[tid];
        float o = 0.0f;                               // pad-with-zero path
        if (isfinite(v) && i < T_LEN) o = (float)spred[i];
        out[(size_t)b * OUT_LEN + tid] = o;
    }
}

// ---------------------------------------------------------------------------
extern "C" void kernel_launch(void* const* d_in, const int* in_sizes, int n_in,
                              void* d_out, int out_size) {
    const float* x = (const float*)d_in[0];
    float* out = (float*)d_out;

    const int n_pos = B_SAMPLES * T_LEN;
    softmax_conf_kernel<<<n_pos / POS_PER_CTA, K1_THREADS>>>(x);
    topk_kernel<<<B_SAMPLES, K2_THREADS>>>(out);
}

// round 17
// speedup vs baseline: 1.3960x; 1.0006x over previous
#include <cuda_runtime.h>
#include <math.h>

#define B_SAMPLES 128
#define T_LEN     8192
#define C_CLASSES 64
#define OUT_LEN   8

#define K1_THREADS 256
#define POS_PER_CTA (K1_THREADS / 4)            // 4 threads per position
#define K2_THREADS 1024
#define EPT 8                                    // contiguous elems per thread
#define L2E 1.4426950408889634f

// Scratch (allocation-free __device__ globals)
__device__ __align__(16) float         g_conf[B_SAMPLES * T_LEN];
__device__ __align__(16) unsigned char g_pred[B_SAMPLES * T_LEN];

__device__ __forceinline__ float ex2_approx(float t) {
    float r;
    asm("ex2.approx.ftz.f32 %0, %1;" : "=f"(r) : "f"(t));
    return r;
}
__device__ __forceinline__ unsigned long long mk_evict_last_policy() {
    unsigned long long pol;
    asm("createpolicy.fractional.L2::evict_last.b64 %0, 1.0;" : "=l"(pol));
    return pol;
}
__device__ __forceinline__ void st_el_f32(float* p, float v, unsigned long long pol) {
    asm volatile("st.global.L2::cache_hint.f32 [%0], %1, %2;"
                 :: "l"(p), "f"(v), "l"(pol) : "memory");
}
__device__ __forceinline__ void st_el_u8(unsigned char* p, unsigned short v,
                                         unsigned long long pol) {
    asm volatile("st.global.L2::cache_hint.u8 [%0], %1, %2;"
                 :: "l"(p), "h"(v), "l"(pol) : "memory");
}

// ---------------------------------------------------------------------------
// K1: byte-for-byte the R10 kernel (best known: ~40us, DRAM ~80%)
// + PDL trigger as the final instruction (launch timing only, zero overhead).
// ---------------------------------------------------------------------------
__global__ __launch_bounds__(K1_THREADS)
void softmax_conf_kernel(const float* __restrict__ x) {
    const int tid  = threadIdx.x;
    const int part = tid & 3;
    const size_t pos = (size_t)blockIdx.x * POS_PER_CTA + (tid >> 2);

    const float4* __restrict__ p =
        (const float4*)(x + pos * C_CLASSES + part * 16);
    float4 v0 = p[0], v1 = p[1], v2 = p[2], v3 = p[3];

    float r[16] = {v0.x, v0.y, v0.z, v0.w, v1.x, v1.y, v1.z, v1.w,
                   v2.x, v2.y, v2.z, v2.w, v3.x, v3.y, v3.z, v3.w};

    float m = r[0];
    #pragma unroll
    for (int c = 1; c < 16; c++) m = fmaxf(m, r[c]);

    int am = 0;                                   // first-occurrence argmax
    #pragma unroll
    for (int c = 15; c >= 0; c--)
        if (r[c] >= m) am = c;
    int amg = part * 16 + am;

    #pragma unroll
    for (int d = 1; d < 4; d <<= 1) {
        float om = __shfl_xor_sync(0xFFFFFFFFu, m,   d);
        int   oa = __shfl_xor_sync(0xFFFFFFFFu, amg, d);
        if (om > m || (om == m && oa < amg)) { m = om; amg = oa; }
    }

    float mb = m * L2E;
    float s = 0.0f;
    #pragma unroll
    for (int c = 0; c < 16; c++)
        s += ex2_approx(fmaf(r[c], L2E, -mb));
    #pragma unroll
    for (int d = 1; d < 4; d <<= 1)
        s += __shfl_xor_sync(0xFFFFFFFFu, s, d);

    if (part == 0) {
        unsigned long long pol = mk_evict_last_policy();
        st_el_f32(&g_conf[pos], __fdividef(1.0f, s), pol);
        st_el_u8(&g_pred[pos], (unsigned short)amg, pol);
    }

    // PDL: allow the dependent kernel's CTAs to be scheduled as we drain.
    asm volatile("griddepcontrol.launch_dependents;");
}

// ---------------------------------------------------------------------------
// K2: per-sample RLE + top-8 (R16 mask-consume version) with PDL wait at head.
// ---------------------------------------------------------------------------
__global__ __launch_bounds__(K2_THREADS)
void topk_kernel(float* __restrict__ out) {
    __shared__ unsigned char spred[T_LEN];           // 8 KB
    __shared__ float candv[OUT_LEN * 32];            // [round][warp]
    __shared__ int   candi[OUT_LEN * 32];
    __shared__ float outv[OUT_LEN];
    __shared__ int   outi[OUT_LEN];

    // PDL: wait for K1 completion + memory visibility before any read.
    asm volatile("griddepcontrol.wait;" ::: "memory");

    const int b    = blockIdx.x;
    const int tid  = threadIdx.x;
    const int lane = tid & 31;
    const int wid  = tid >> 5;
    const size_t off = (size_t)b * T_LEN;
    const int t0 = tid * EPT;

    // ---- Front-batched, unconditional loads (L2-warm: just stored) ----
    uint2  pv2 = ((const uint2*)(g_pred + off))[tid];
    float4 c0  = ((const float4*)(g_conf + off))[tid * 2];
    float4 c1  = ((const float4*)(g_conf + off))[tid * 2 + 1];

    ((uint2*)spred)[tid] = pv2;
    __syncthreads();

    unsigned char pb[EPT];
    pb[0] = (unsigned char)(pv2.x);        pb[1] = (unsigned char)(pv2.x >> 8);
    pb[2] = (unsigned char)(pv2.x >> 16);  pb[3] = (unsigned char)(pv2.x >> 24);
    pb[4] = (unsigned char)(pv2.y);        pb[5] = (unsigned char)(pv2.y >> 8);
    pb[6] = (unsigned char)(pv2.y >> 16);  pb[7] = (unsigned char)(pv2.y >> 24);
    float cf[EPT] = {c0.x, c0.y, c0.z, c0.w, c1.x, c1.y, c1.z, c1.w};

    unsigned char prev = (tid == 0) ? (unsigned char)(pb[0] ^ 1) : spred[t0 - 1];

    float lv[EPT];
    #pragma unroll
    for (int j = 0; j < EPT; j++) {
        unsigned char cur = pb[j];
        unsigned char before = (j == 0) ? prev : pb[j - 1];
        bool start = (t0 + j == 0) || (cur != before);
        float v = -INFINITY;
        if (start) {
            int cnt = 1;
            int jj = j + 1;
            while (jj < EPT && pb[jj] == cur) { cnt++; jj++; }   // reg scan
            if (jj == EPT) {                                      // rare spill
                int e = t0 + EPT;
                while (e < T_LEN && spred[e] == cur) { cnt++; e++; }
            }
            v = cf[j] * (float)cnt;
        }
        lv[j] = v;
    }

    // ---- Phase A: per-warp top-8 (mask-consume, static indexing only) ----
    unsigned mask = 0;                   // bit j set = lv[j] consumed
    #pragma unroll
    for (int k = 0; k < OUT_LEN; k++) {
        float bv = -INFINITY;
        int   bj = 0;
        #pragma unroll
        for (int j = 0; j < EPT; j++)    // j asc = index asc (first-max tie)
            if (!(mask & (1u << j)) && lv[j] > bv) { bv = lv[j]; bj = j; }
        int bi = t0 + bj;

        #pragma unroll
        for (int d = 16; d > 0; d >>= 1) {
            float ov = __shfl_xor_sync(0xFFFFFFFFu, bv, d);
            int   oi = __shfl_xor_sync(0xFFFFFFFFu, bi, d);
            if (ov > bv || (ov == bv && oi < bi)) { bv = ov; bi = oi; }
        }
        if (lane == 0) {
            candv[k * 32 + wid] = bv;
            candi[k * 32 + wid] = bi;
        }
        if ((bi >> 3) == tid)            // owner consumes
            mask |= 1u << (bi & (EPT - 1));
    }
    __syncthreads();

    // ---- Phase B: warp 0 merges 32x8 candidates (mask-consume) ----
    if (wid == 0) {
        float cv[OUT_LEN];
        int   ci[OUT_LEN];
        #pragma unroll
        for (int r = 0; r < OUT_LEN; r++) {
            cv[r] = candv[r * 32 + lane];
            ci[r] = candi[r * 32 + lane];
        }
        unsigned m2 = 0;
        #pragma unroll
        for (int k = 0; k < OUT_LEN; k++) {
            float bv = -INFINITY;
            int   bi = 0x7FFFFFFF, br = 0;
            #pragma unroll
            for (int r = 0; r < OUT_LEN; r++)
                if (!(m2 & (1u << r)) && cv[r] > bv) {
                    bv = cv[r]; bi = ci[r]; br = r;
                }
            float mv = bv; int mi = bi;
            #pragma unroll
            for (int d = 16; d > 0; d >>= 1) {
                float ov = __shfl_xor_sync(0xFFFFFFFFu, mv, d);
                int   oi = __shfl_xor_sync(0xFFFFFFFFu, mi, d);
                if (ov > mv || (ov == mv && oi < mi)) { mv = ov; mi = oi; }
            }
            if (lane == 0) { outv[k] = mv; outi[k] = mi; }
            if (bv == mv && bi == mi)    // unique index -> exactly one owner
                m2 |= 1u << br;
        }
    }
    __syncthreads();

    if (tid < OUT_LEN) {
        float v = outv[tid];
        int   i = outi[tid];
        float o = 0.0f;                               // pad-with-zero path
        if (isfinite(v) && i < T_LEN) o = (float)spred[i];
        out[(size_t)b * OUT_LEN + tid] = o;
    }
}

// ---------------------------------------------------------------------------
extern "C" void kernel_launch(void* const* d_in, const int* in_sizes, int n_in,
                              void* d_out, int out_size) {
    const float* x = (const float*)d_in[0];
    float* out = (float*)d_out;

    const int n_pos = B_SAMPLES * T_LEN;
    softmax_conf_kernel<<<n_pos / POS_PER_CTA, K1_THREADS>>>(x);

    // K2 with programmatic dependent launch: dispatch while K1 drains.
    cudaLaunchConfig_t cfg = {};
    cfg.gridDim  = dim3(B_SAMPLES, 1, 1);
    cfg.blockDim = dim3(K2_THREADS, 1, 1);
    cfg.dynamicSmemBytes = 0;
    cfg.stream = 0;
    cudaLaunchAttribute attrs[1];
    attrs[0].id = cudaLaunchAttributeProgrammaticStreamSerialization;
    attrs[0].val.programmaticStreamSerializationAllowed = 1;
    cfg.attrs = attrs;
    cfg.numAttrs = 1;
    cudaLaunchKernelEx(&cfg, topk_kernel, out);
}